// round 10
// baseline (speedup 1.0000x reference)
#include <cuda_runtime.h>
#include <cuda_bf16.h>
#include <cuda_fp8.h>
#include <cstdint>

#define IDIM 1024
#define ODIM 1024
#define NDEG 9
#define KG 8192            // bf16 GEMM K (j = 1..8)
#define K8 16384           // fp8 correction virtual K ([Ah|Al] x [Bl|Bh])
#define BMAX 8192

// scales: Ah8 = Ah*64, Al8 = Al*8192, Bl8 = Bl*8192, Bh8 = Bh*64
// both product scales = 64*8192 = 2^19
#define CORR_INV (1.0f / 524288.0f)

// ---------------- device scratch (static globals: allocation-guard safe) ----
__device__ __nv_bfloat16 g_Th[(size_t)BMAX * KG];
__device__ __nv_bfloat16 g_Tl[(size_t)BMAX * KG];
__device__ __nv_bfloat16 g_Bh[(size_t)ODIM * KG];
__device__ __nv_bfloat16 g_Bl[(size_t)ODIM * KG];
__device__ uint16_t g_A8[(size_t)BMAX * (K8 / 2)];   // fp8x2: [Ah8 | Al8]
__device__ uint16_t g_B8[(size_t)ODIM * (K8 / 2)];   // fp8x2: [Bl8 | Bh8]
__device__ float g_bias[ODIM];

__device__ __forceinline__ uint16_t f2_e4m3x2(float lo, float hi) {
    return __nv_cvt_float2_to_fp8x2(make_float2(lo, hi), __NV_SATFINITE, __NV_E4M3);
}

// ---------------------------------------------------------------------------
// Kernel 1: fused row min/max + Chebyshev basis; bf16 hi/lo (j>=1) + fp8
// ---------------------------------------------------------------------------
__global__ void __launch_bounds__(256) buildT_kernel(const float* __restrict__ x) {
    const int b = blockIdx.x;
    const int tid = threadIdx.x;
    const float* row = x + (size_t)b * IDIM;

    float2 v[2];
    #pragma unroll
    for (int s = 0; s < 2; s++)
        v[s] = *(const float2*)(row + 2 * (tid + 256 * s));

    float mn = fminf(fminf(v[0].x, v[0].y), fminf(v[1].x, v[1].y));
    float mx = fmaxf(fmaxf(v[0].x, v[0].y), fmaxf(v[1].x, v[1].y));
    #pragma unroll
    for (int o = 16; o; o >>= 1) {
        mn = fminf(mn, __shfl_xor_sync(0xFFFFFFFFu, mn, o));
        mx = fmaxf(mx, __shfl_xor_sync(0xFFFFFFFFu, mx, o));
    }
    __shared__ float smn[8], smx[8];
    int w = tid >> 5, l = tid & 31;
    if (l == 0) { smn[w] = mn; smx[w] = mx; }
    __syncthreads();
    #pragma unroll
    for (int i = 0; i < 8; i++) { mn = fminf(mn, smn[i]); mx = fmaxf(mx, smx[i]); }
    const float sc = 2.0f / (mx - mn);

    const size_t baseB = (size_t)b * KG;
    const size_t base8 = (size_t)b * (K8 / 2);
    #pragma unroll
    for (int s = 0; s < 2; s++) {
        int p = tid + 256 * s;
        float xa = (v[s].x - mn) * sc - 1.0f;
        float xb = (v[s].y - mn) * sc - 1.0f;
        float a0 = 1.0f, a1 = xa, b0 = 1.0f, b1 = xb;
        #pragma unroll
        for (int j = 1; j < NDEG; j++) {
            float ta = a1, tb = b1;
            __nv_bfloat16 ha = __float2bfloat16(ta);
            __nv_bfloat16 hb = __float2bfloat16(tb);
            float hfa = __bfloat162float(ha);
            float hfb = __bfloat162float(hb);
            float la = ta - hfa, lb = tb - hfb;
            __nv_bfloat162 hi2, lo2;
            hi2.x = ha; hi2.y = hb;
            lo2.x = __float2bfloat16(la);
            lo2.y = __float2bfloat16(lb);
            size_t off = baseB + (size_t)(j - 1) * IDIM + 2 * p;
            *(__nv_bfloat162*)(g_Th + off) = hi2;
            *(__nv_bfloat162*)(g_Tl + off) = lo2;
            // fp8: Ah8 (hi*64) and Al8 (lo*8192); pair index = off/2
            size_t p8 = base8 + (size_t)(j - 1) * (IDIM / 2) + p;
            g_A8[p8] = f2_e4m3x2(hfa * 64.0f, hfb * 64.0f);
            g_A8[p8 + KG / 2] = f2_e4m3x2(la * 8192.0f, lb * 8192.0f);
            float na = 2.0f * xa * a1 - a0; a0 = a1; a1 = na;
            float nb = 2.0f * xb * b1 - b0; b0 = b1; b1 = nb;
        }
    }
}

// ---------------------------------------------------------------------------
// Kernel 2: coeffs [i][o][j] -> Bh/Bl bf16 (j>=1) + fp8 [Bl8|Bh8]
// ---------------------------------------------------------------------------
__global__ void transC_kernel(const float* __restrict__ c) {
    int idx = blockIdx.x * blockDim.x + threadIdx.x;
    if (idx >= ODIM * (IDIM / 2)) return;
    int o = idx >> 9;
    int p = idx & 511;
    const float* s0 = c + ((size_t)(2 * p) * ODIM + o) * NDEG;
    const float* s1 = c + ((size_t)(2 * p + 1) * ODIM + o) * NDEG;
    size_t baseB = (size_t)o * KG + 2 * p;
    size_t base8 = (size_t)o * (K8 / 2) + p;
    #pragma unroll
    for (int j = 1; j < NDEG; j++) {
        float va = s0[j], vb = s1[j];
        __nv_bfloat16 ha = __float2bfloat16(va);
        __nv_bfloat16 hb = __float2bfloat16(vb);
        float hfa = __bfloat162float(ha);
        float hfb = __bfloat162float(hb);
        float la = va - hfa, lb = vb - hfb;
        __nv_bfloat162 hi2, lo2;
        hi2.x = ha; hi2.y = hb;
        lo2.x = __float2bfloat16(la);
        lo2.y = __float2bfloat16(lb);
        size_t off = baseB + (size_t)(j - 1) * IDIM;
        *(__nv_bfloat162*)(g_Bh + off) = hi2;
        *(__nv_bfloat162*)(g_Bl + off) = lo2;
        size_t p8 = base8 + (size_t)(j - 1) * (IDIM / 2);
        g_B8[p8] = f2_e4m3x2(la * 8192.0f, lb * 8192.0f);      // Bl8
        g_B8[p8 + KG / 2] = f2_e4m3x2(hfa * 64.0f, hfb * 64.0f); // Bh8
    }
}

// ---------------------------------------------------------------------------
// Kernel 3: bias[o] = sum_i c[i][o][0]  (deterministic block reduction)
// ---------------------------------------------------------------------------
__global__ void __launch_bounds__(256) bias_kernel(const float* __restrict__ c) {
    const int o = blockIdx.x;
    float s = 0.0f;
    for (int i = threadIdx.x; i < IDIM; i += 256)
        s += c[((size_t)i * ODIM + o) * NDEG];
    #pragma unroll
    for (int w = 16; w; w >>= 1) s += __shfl_xor_sync(0xFFFFFFFFu, s, w);
    __shared__ float sh[8];
    if ((threadIdx.x & 31) == 0) sh[threadIdx.x >> 5] = s;
    __syncthreads();
    if (threadIdx.x == 0) {
        float t = 0.0f;
        #pragma unroll
        for (int i = 0; i < 8; i++) t += sh[i];
        g_bias[o] = t;
    }
}

// ---------------------------------------------------------------------------
// GEMM common
// ---------------------------------------------------------------------------
#define TILE_M 128
#define TILE_N 256
#define ROWPB 144
#define A_ST (TILE_M * ROWPB)       // 18432
#define B_ST (TILE_N * ROWPB)       // 36864
#define STAGE (A_ST + B_ST)         // 55296
#define SMEM_TOTAL (2 * STAGE)      // 110592

__device__ __forceinline__ uint32_t smem_u32(const void* p) {
    uint32_t a;
    asm("{ .reg .u64 t; cvta.to.shared.u64 t, %1; cvt.u32.u64 %0, t; }"
        : "=r"(a) : "l"(p));
    return a;
}
__device__ __forceinline__ void cp16(uint32_t dst, const void* src) {
    asm volatile("cp.async.cg.shared.global [%0], [%1], 16;" :: "r"(dst), "l"(src));
}
__device__ __forceinline__ void ldmx4(uint32_t* r, uint32_t addr) {
    asm volatile("ldmatrix.sync.aligned.m8n8.x4.shared.b16 {%0,%1,%2,%3}, [%4];"
                 : "=r"(r[0]), "=r"(r[1]), "=r"(r[2]), "=r"(r[3]) : "r"(addr));
}
__device__ __forceinline__ void mma_bf16(float* c, const uint32_t* a, const uint32_t* b) {
    asm volatile(
        "mma.sync.aligned.m16n8k16.row.col.f32.bf16.bf16.f32 "
        "{%0,%1,%2,%3}, {%4,%5,%6,%7}, {%8,%9}, {%0,%1,%2,%3};"
        : "+f"(c[0]), "+f"(c[1]), "+f"(c[2]), "+f"(c[3])
        : "r"(a[0]), "r"(a[1]), "r"(a[2]), "r"(a[3]), "r"(b[0]), "r"(b[1]));
}
__device__ __forceinline__ void mma_fp8(float* c, const uint32_t* a, const uint32_t* b) {
    asm volatile(
        "mma.sync.aligned.m16n8k32.row.col.f32.e4m3.e4m3.f32 "
        "{%0,%1,%2,%3}, {%4,%5,%6,%7}, {%8,%9}, {%0,%1,%2,%3};"
        : "+f"(c[0]), "+f"(c[1]), "+f"(c[2]), "+f"(c[3])
        : "r"(a[0]), "r"(a[1]), "r"(a[2]), "r"(a[3]), "r"(b[0]), "r"(b[1]));
}

extern __shared__ char dynsmem[];

// ---------------------------------------------------------------------------
// Kernel 4: fp8 correction GEMM over virtual K=16384; writes out = corr + bias
// ---------------------------------------------------------------------------
#define NQ8 (K8 / 128)              // 128 stages of 128 fp8 elems

__global__ void __launch_bounds__(512, 1) corr_gemm_kernel(float* __restrict__ out) {
    const uint32_t smem_base = smem_u32(dynsmem);
    const int tid = threadIdx.x;
    const int lane = tid & 31;
    const int warp = tid >> 5;
    const int wm = warp & 3;
    const int wn = warp >> 2;

    const int mBase = blockIdx.y * TILE_M;
    const int nBase = blockIdx.x * TILE_N;

    const uint8_t* A8 = (const uint8_t*)g_A8 + (size_t)mBase * K8;
    const uint8_t* B8 = (const uint8_t*)g_B8 + (size_t)nBase * K8;

    const int aRow = (lane & 7) + ((lane >> 3) & 1) * 8;
    const int aK16 = (lane >> 4) & 1;
    const int bRow = (lane & 7) + ((lane >> 4) & 1) * 8;
    const int bK16 = (lane >> 3) & 1;

    float acc[2][8][4];
    #pragma unroll
    for (int mt = 0; mt < 2; mt++)
        #pragma unroll
        for (int nt = 0; nt < 8; nt++)
            #pragma unroll
            for (int j = 0; j < 4; j++)
                acc[mt][nt][j] = 0.0f;

    auto load_stage = [&](int q, int buf) {
        const int k0 = q * 128;
        const uint32_t so = smem_base + buf * STAGE;
        #pragma unroll
        for (int r = 0; r < 2; r++) {
            int c = tid + 512 * r;
            int row = c >> 3, c16 = c & 7;
            cp16(so + row * ROWPB + c16 * 16,
                 A8 + (size_t)row * K8 + k0 + c16 * 16);
        }
        #pragma unroll
        for (int r = 0; r < 4; r++) {
            int c = tid + 512 * r;
            int row = c >> 3, c16 = c & 7;
            cp16(so + A_ST + row * ROWPB + c16 * 16,
                 B8 + (size_t)row * K8 + k0 + c16 * 16);
        }
        asm volatile("cp.async.commit_group;" ::: "memory");
    };

    load_stage(0, 0);

    for (int q = 0; q < NQ8; q++) {
        if (q + 1 < NQ8) {
            load_stage(q + 1, (q + 1) & 1);
            asm volatile("cp.async.wait_group 1;" ::: "memory");
        } else {
            asm volatile("cp.async.wait_group 0;" ::: "memory");
        }
        __syncthreads();

        const uint32_t so = smem_base + (q & 1) * STAGE;
        const uint32_t aBase = so + (wm * 32 + aRow) * ROWPB + aK16 * 16;
        const uint32_t bBase = so + A_ST + (wn * 64 + bRow) * ROWPB + bK16 * 16;

        #pragma unroll
        for (int kk = 0; kk < 128; kk += 32) {
            uint32_t a8[2][4];
            uint32_t b8[8][2];
            #pragma unroll
            for (int mt = 0; mt < 2; mt++)
                ldmx4(a8[mt], aBase + mt * 16 * ROWPB + kk);
            #pragma unroll
            for (int nt2 = 0; nt2 < 4; nt2++) {
                uint32_t r[4];
                ldmx4(r, bBase + nt2 * 16 * ROWPB + kk);
                b8[nt2*2+0][0] = r[0]; b8[nt2*2+0][1] = r[1];
                b8[nt2*2+1][0] = r[2]; b8[nt2*2+1][1] = r[3];
            }
            #pragma unroll
            for (int mt = 0; mt < 2; mt++)
                #pragma unroll
                for (int nt = 0; nt < 8; nt++)
                    mma_fp8(acc[mt][nt], a8[mt], b8[nt]);
        }
        __syncthreads();
    }

    const int mW = mBase + wm * 32;
    const int nW = nBase + wn * 64;
    #pragma unroll
    for (int mt = 0; mt < 2; mt++) {
        #pragma unroll
        for (int nt = 0; nt < 8; nt++) {
            int row0 = mW + mt * 16 + (lane >> 2);
            int col  = nW + nt * 8 + (lane & 3) * 2;
            float b0 = g_bias[col], b1 = g_bias[col + 1];
            *(float2*)(out + (size_t)row0 * ODIM + col) =
                make_float2(acc[mt][nt][0] * CORR_INV + b0,
                            acc[mt][nt][1] * CORR_INV + b1);
            *(float2*)(out + (size_t)(row0 + 8) * ODIM + col) =
                make_float2(acc[mt][nt][2] * CORR_INV + b0,
                            acc[mt][nt][3] * CORR_INV + b1);
        }
    }
}

// ---------------------------------------------------------------------------
// Kernel 5: main bf16 GEMM (Ah x Bh), K=8192; out += acc
// ---------------------------------------------------------------------------
#define NQG (KG / 64)               // 128 stages of 64 bf16 elems

__global__ void __launch_bounds__(512, 1) main_gemm_kernel(float* __restrict__ out) {
    const uint32_t smem_base = smem_u32(dynsmem);
    const int tid = threadIdx.x;
    const int lane = tid & 31;
    const int warp = tid >> 5;
    const int wm = warp & 3;
    const int wn = warp >> 2;

    const int mBase = blockIdx.y * TILE_M;
    const int nBase = blockIdx.x * TILE_N;

    const __nv_bfloat16* Ah = g_Th + (size_t)mBase * KG;
    const __nv_bfloat16* Bh = g_Bh + (size_t)nBase * KG;

    const int aRow = (lane & 7) + ((lane >> 3) & 1) * 8;
    const int aK8  = (lane >> 4) & 1;
    const int bRow = (lane & 7) + ((lane >> 4) & 1) * 8;
    const int bK8  = (lane >> 3) & 1;

    float acc[2][8][4];
    #pragma unroll
    for (int mt = 0; mt < 2; mt++)
        #pragma unroll
        for (int nt = 0; nt < 8; nt++)
            #pragma unroll
            for (int j = 0; j < 4; j++)
                acc[mt][nt][j] = 0.0f;

    auto load_stage = [&](int q, int buf) {
        const int k0 = q * 64;
        const uint32_t so = smem_base + buf * STAGE;
        #pragma unroll
        for (int r = 0; r < 2; r++) {
            int c = tid + 512 * r;
            int row = c >> 3, c16 = c & 7;
            cp16(so + row * ROWPB + c16 * 16,
                 Ah + (size_t)row * KG + k0 + c16 * 8);
        }
        #pragma unroll
        for (int r = 0; r < 4; r++) {
            int c = tid + 512 * r;
            int row = c >> 3, c16 = c & 7;
            cp16(so + A_ST + row * ROWPB + c16 * 16,
                 Bh + (size_t)row * KG + k0 + c16 * 8);
        }
        asm volatile("cp.async.commit_group;" ::: "memory");
    };

    load_stage(0, 0);

    for (int q = 0; q < NQG; q++) {
        if (q + 1 < NQG) {
            load_stage(q + 1, (q + 1) & 1);
            asm volatile("cp.async.wait_group 1;" ::: "memory");
        } else {
            asm volatile("cp.async.wait_group 0;" ::: "memory");
        }
        __syncthreads();

        const uint32_t so = smem_base + (q & 1) * STAGE;
        const uint32_t aBase = so + (wm * 32 + aRow) * ROWPB + aK8 * 16;
        const uint32_t bBase = so + A_ST + (wn * 64 + bRow) * ROWPB + bK8 * 16;

        #pragma unroll
        for (int kk = 0; kk < 64; kk += 16) {
            uint32_t af[2][4];
            uint32_t bf[8][2];
            #pragma unroll
            for (int mt = 0; mt < 2; mt++)
                ldmx4(af[mt], aBase + mt * 16 * ROWPB + kk * 2);
            #pragma unroll
            for (int nt2 = 0; nt2 < 4; nt2++) {
                uint32_t r[4];
                ldmx4(r, bBase + nt2 * 16 * ROWPB + kk * 2);
                bf[nt2*2+0][0] = r[0]; bf[nt2*2+0][1] = r[1];
                bf[nt2*2+1][0] = r[2]; bf[nt2*2+1][1] = r[3];
            }
            #pragma unroll
            for (int mt = 0; mt < 2; mt++)
                #pragma unroll
                for (int nt = 0; nt < 8; nt++)
                    mma_bf16(acc[mt][nt], af[mt], bf[nt]);
        }
        __syncthreads();
    }

    const int mW = mBase + wm * 32;
    const int nW = nBase + wn * 64;
    #pragma unroll
    for (int mt = 0; mt < 2; mt++) {
        #pragma unroll
        for (int nt = 0; nt < 8; nt++) {
            int row0 = mW + mt * 16 + (lane >> 2);
            int col  = nW + nt * 8 + (lane & 3) * 2;
            float2* p0 = (float2*)(out + (size_t)row0 * ODIM + col);
            float2* p1 = (float2*)(out + (size_t)(row0 + 8) * ODIM + col);
            float2 v0 = *p0, v1 = *p1;
            v0.x += acc[mt][nt][0]; v0.y += acc[mt][nt][1];
            v1.x += acc[mt][nt][2]; v1.y += acc[mt][nt][3];
            *p0 = v0;
            *p1 = v1;
        }
    }
}

// ---------------------------------------------------------------------------
extern "C" void kernel_launch(void* const* d_in, const int* in_sizes, int n_in,
                              void* d_out, int out_size) {
    const float* x = (const float*)d_in[0];
    const float* coeffs = (const float*)d_in[1];
    float* out = (float*)d_out;

    int nb = in_sizes[0] / IDIM;   // 8192

    cudaFuncSetAttribute(corr_gemm_kernel,
                         cudaFuncAttributeMaxDynamicSharedMemorySize, SMEM_TOTAL);
    cudaFuncSetAttribute(main_gemm_kernel,
                         cudaFuncAttributeMaxDynamicSharedMemorySize, SMEM_TOTAL);

    buildT_kernel<<<nb, 256>>>(x);
    transC_kernel<<<(ODIM * (IDIM / 2) + 255) / 256, 256>>>(coeffs);
    bias_kernel<<<ODIM, 256>>>(coeffs);

    dim3 grid(ODIM / TILE_N, nb / TILE_M);   // (4, 64)
    corr_gemm_kernel<<<grid, 512, SMEM_TOTAL>>>(out);
    main_gemm_kernel<<<grid, 512, SMEM_TOTAL>>>(out);
}

// round 11
// speedup vs baseline: 2.7792x; 2.7792x over previous
#include <cuda_runtime.h>
#include <cuda_fp16.h>
#include <cstdint>

#define IDIM 1024
#define ODIM 1024
#define NDEG 9
#define KG 8192            // GEMM K (Chebyshev j = 1..8); T0 handled as bias
#define BMAX 8192

// ---------------- device scratch (static globals: allocation-guard safe) ----
__device__ __half g_A[(size_t)BMAX * KG];   // T basis fp16, k = (j-1)*1024 + i
__device__ __half g_B[(size_t)ODIM * KG];   // coeffs fp16,  [o][k]
__device__ float g_bias[ODIM];

// ---------------------------------------------------------------------------
// Kernel 1: fused row min/max + Chebyshev basis -> fp16, k=(j-1)*1024+i
// ---------------------------------------------------------------------------
__global__ void __launch_bounds__(256) buildT_kernel(const float* __restrict__ x) {
    const int b = blockIdx.x;
    const int tid = threadIdx.x;
    const float* row = x + (size_t)b * IDIM;

    float2 v[2];
    #pragma unroll
    for (int s = 0; s < 2; s++)
        v[s] = *(const float2*)(row + 2 * (tid + 256 * s));

    float mn = fminf(fminf(v[0].x, v[0].y), fminf(v[1].x, v[1].y));
    float mx = fmaxf(fmaxf(v[0].x, v[0].y), fmaxf(v[1].x, v[1].y));
    #pragma unroll
    for (int o = 16; o; o >>= 1) {
        mn = fminf(mn, __shfl_xor_sync(0xFFFFFFFFu, mn, o));
        mx = fmaxf(mx, __shfl_xor_sync(0xFFFFFFFFu, mx, o));
    }
    __shared__ float smn[8], smx[8];
    int w = tid >> 5, l = tid & 31;
    if (l == 0) { smn[w] = mn; smx[w] = mx; }
    __syncthreads();
    #pragma unroll
    for (int i = 0; i < 8; i++) { mn = fminf(mn, smn[i]); mx = fmaxf(mx, smx[i]); }
    const float sc = 2.0f / (mx - mn);

    const size_t base = (size_t)b * KG;
    #pragma unroll
    for (int s = 0; s < 2; s++) {
        int p = tid + 256 * s;
        float xa = (v[s].x - mn) * sc - 1.0f;
        float xb = (v[s].y - mn) * sc - 1.0f;
        float a0 = 1.0f, a1 = xa, b0 = 1.0f, b1 = xb;
        #pragma unroll
        for (int j = 1; j < NDEG; j++) {
            __half2 h2;
            h2.x = __float2half_rn(a1);
            h2.y = __float2half_rn(b1);
            *(__half2*)(g_A + base + (size_t)(j - 1) * IDIM + 2 * p) = h2;
            float na = 2.0f * xa * a1 - a0; a0 = a1; a1 = na;
            float nb = 2.0f * xb * b1 - b0; b0 = b1; b1 = nb;
        }
    }
}

// ---------------------------------------------------------------------------
// Kernel 2: coeffs [i][o][j] -> B[o][k=(j-1)*1024+i] fp16
// ---------------------------------------------------------------------------
__global__ void transC_kernel(const float* __restrict__ c) {
    int idx = blockIdx.x * blockDim.x + threadIdx.x;
    if (idx >= ODIM * (IDIM / 2)) return;
    int o = idx >> 9;
    int p = idx & 511;
    const float* s0 = c + ((size_t)(2 * p) * ODIM + o) * NDEG;
    const float* s1 = c + ((size_t)(2 * p + 1) * ODIM + o) * NDEG;
    size_t base = (size_t)o * KG + 2 * p;
    #pragma unroll
    for (int j = 1; j < NDEG; j++) {
        __half2 h2;
        h2.x = __float2half_rn(s0[j]);
        h2.y = __float2half_rn(s1[j]);
        *(__half2*)(g_B + base + (size_t)(j - 1) * IDIM) = h2;
    }
}

// ---------------------------------------------------------------------------
// Kernel 3: bias[o] = sum_i c[i][o][0]   (T0 == 1 contribution, exact fp32)
// ---------------------------------------------------------------------------
__global__ void __launch_bounds__(256) bias_kernel(const float* __restrict__ c) {
    const int o = blockIdx.x;
    float s = 0.0f;
    for (int i = threadIdx.x; i < IDIM; i += 256)
        s += c[((size_t)i * ODIM + o) * NDEG];
    #pragma unroll
    for (int w = 16; w; w >>= 1) s += __shfl_xor_sync(0xFFFFFFFFu, s, w);
    __shared__ float sh[8];
    if ((threadIdx.x & 31) == 0) sh[threadIdx.x >> 5] = s;
    __syncthreads();
    if (threadIdx.x == 0) {
        float t = 0.0f;
        #pragma unroll
        for (int i = 0; i < 8; i++) t += sh[i];
        g_bias[o] = t;
    }
}

// ---------------------------------------------------------------------------
// Kernel 4: fp16 GEMM  out[M,O] = A[M,K] * B[O,K]^T + bias
// CTA 128x256, 512 thr, warp 32x64, 2-stage cp.async (proven structure)
// ---------------------------------------------------------------------------
#define TILE_M 128
#define TILE_N 256
#define NQG (KG / 64)               // 128 stages of 64 elems
#define ROWPB 144
#define A_ST (TILE_M * ROWPB)       // 18432
#define B_ST (TILE_N * ROWPB)       // 36864
#define STAGE (A_ST + B_ST)         // 55296
#define SMEM_TOTAL (2 * STAGE)      // 110592

__device__ __forceinline__ uint32_t smem_u32(const void* p) {
    uint32_t a;
    asm("{ .reg .u64 t; cvta.to.shared.u64 t, %1; cvt.u32.u64 %0, t; }"
        : "=r"(a) : "l"(p));
    return a;
}
__device__ __forceinline__ void cp16(uint32_t dst, const void* src) {
    asm volatile("cp.async.cg.shared.global [%0], [%1], 16;" :: "r"(dst), "l"(src));
}
__device__ __forceinline__ void ldmx4(uint32_t* r, uint32_t addr) {
    asm volatile("ldmatrix.sync.aligned.m8n8.x4.shared.b16 {%0,%1,%2,%3}, [%4];"
                 : "=r"(r[0]), "=r"(r[1]), "=r"(r[2]), "=r"(r[3]) : "r"(addr));
}
__device__ __forceinline__ void mma_f16(float* c, const uint32_t* a, const uint32_t* b) {
    asm volatile(
        "mma.sync.aligned.m16n8k16.row.col.f32.f16.f16.f32 "
        "{%0,%1,%2,%3}, {%4,%5,%6,%7}, {%8,%9}, {%0,%1,%2,%3};"
        : "+f"(c[0]), "+f"(c[1]), "+f"(c[2]), "+f"(c[3])
        : "r"(a[0]), "r"(a[1]), "r"(a[2]), "r"(a[3]), "r"(b[0]), "r"(b[1]));
}

extern __shared__ char dynsmem[];

__global__ void __launch_bounds__(512, 1) gemm_kernel(float* __restrict__ out) {
    const uint32_t smem_base = smem_u32(dynsmem);
    const int tid = threadIdx.x;
    const int lane = tid & 31;
    const int warp = tid >> 5;
    const int wm = warp & 3;         // M band: 32*wm
    const int wn = warp >> 2;        // N band: 64*wn

    const int mBase = blockIdx.y * TILE_M;
    const int nBase = blockIdx.x * TILE_N;

    const __half* Ag = g_A + (size_t)mBase * KG;
    const __half* Bg = g_B + (size_t)nBase * KG;

    const int aRow = (lane & 7) + ((lane >> 3) & 1) * 8;
    const int aK8  = (lane >> 4) & 1;
    const int bRow = (lane & 7) + ((lane >> 4) & 1) * 8;
    const int bK8  = (lane >> 3) & 1;

    float acc[2][8][4];
    #pragma unroll
    for (int mt = 0; mt < 2; mt++)
        #pragma unroll
        for (int nt = 0; nt < 8; nt++)
            #pragma unroll
            for (int j = 0; j < 4; j++)
                acc[mt][nt][j] = 0.0f;

    auto load_stage = [&](int q, int buf) {
        const int k0 = q * 64;
        const uint32_t so = smem_base + buf * STAGE;
        #pragma unroll
        for (int r = 0; r < 2; r++) {
            int c = tid + 512 * r;
            int row = c >> 3, c16 = c & 7;
            cp16(so + row * ROWPB + c16 * 16,
                 Ag + (size_t)row * KG + k0 + c16 * 8);
        }
        #pragma unroll
        for (int r = 0; r < 4; r++) {
            int c = tid + 512 * r;
            int row = c >> 3, c16 = c & 7;
            cp16(so + A_ST + row * ROWPB + c16 * 16,
                 Bg + (size_t)row * KG + k0 + c16 * 8);
        }
        asm volatile("cp.async.commit_group;" ::: "memory");
    };

    load_stage(0, 0);

    for (int q = 0; q < NQG; q++) {
        if (q + 1 < NQG) {
            load_stage(q + 1, (q + 1) & 1);
            asm volatile("cp.async.wait_group 1;" ::: "memory");
        } else {
            asm volatile("cp.async.wait_group 0;" ::: "memory");
        }
        __syncthreads();

        const uint32_t so = smem_base + (q & 1) * STAGE;
        const uint32_t aBase = so + (wm * 32 + aRow) * ROWPB + aK8 * 16;
        const uint32_t bBase = so + A_ST + (wn * 64 + bRow) * ROWPB + bK8 * 16;

        #pragma unroll
        for (int kk = 0; kk < 64; kk += 16) {
            uint32_t af[2][4];
            uint32_t bf[8][2];
            #pragma unroll
            for (int mt = 0; mt < 2; mt++)
                ldmx4(af[mt], aBase + mt * 16 * ROWPB + kk * 2);
            #pragma unroll
            for (int nt2 = 0; nt2 < 4; nt2++) {
                uint32_t r[4];
                ldmx4(r, bBase + nt2 * 16 * ROWPB + kk * 2);
                bf[nt2*2+0][0] = r[0]; bf[nt2*2+0][1] = r[1];
                bf[nt2*2+1][0] = r[2]; bf[nt2*2+1][1] = r[3];
            }
            #pragma unroll
            for (int mt = 0; mt < 2; mt++)
                #pragma unroll
                for (int nt = 0; nt < 8; nt++)
                    mma_f16(acc[mt][nt], af[mt], bf[nt]);
        }
        __syncthreads();
    }

    // epilogue: out = acc + bias
    const int mW = mBase + wm * 32;
    const int nW = nBase + wn * 64;
    #pragma unroll
    for (int mt = 0; mt < 2; mt++) {
        #pragma unroll
        for (int nt = 0; nt < 8; nt++) {
            int row0 = mW + mt * 16 + (lane >> 2);
            int col  = nW + nt * 8 + (lane & 3) * 2;
            float b0 = g_bias[col], b1 = g_bias[col + 1];
            *(float2*)(out + (size_t)row0 * ODIM + col) =
                make_float2(acc[mt][nt][0] + b0, acc[mt][nt][1] + b1);
            *(float2*)(out + (size_t)(row0 + 8) * ODIM + col) =
                make_float2(acc[mt][nt][2] + b0, acc[mt][nt][3] + b1);
        }
    }
}

// ---------------------------------------------------------------------------
extern "C" void kernel_launch(void* const* d_in, const int* in_sizes, int n_in,
                              void* d_out, int out_size) {
    const float* x = (const float*)d_in[0];
    const float* coeffs = (const float*)d_in[1];
    float* out = (float*)d_out;

    int nb = in_sizes[0] / IDIM;   // 8192

    cudaFuncSetAttribute(gemm_kernel,
                         cudaFuncAttributeMaxDynamicSharedMemorySize, SMEM_TOTAL);

    buildT_kernel<<<nb, 256>>>(x);
    transC_kernel<<<(ODIM * (IDIM / 2) + 255) / 256, 256>>>(coeffs);
    bias_kernel<<<ODIM, 256>>>(coeffs);

    dim3 grid(ODIM / TILE_N, nb / TILE_M);   // (4, 64)
    gemm_kernel<<<grid, 512, SMEM_TOTAL>>>(out);
}